// round 7
// baseline (speedup 1.0000x reference)
#include <cuda_runtime.h>
#include <cstdint>

#define IN_DIM   64
#define HID_DIM  256
#define OUT_DIM  128
#define TM       128
#define NTH      256
#define NSM      148
#define INV256   0.00390625f

// fragment array sizes (uint2 elements)
#define W1H_N   (32 * 4 * 32)      // bf16 main  [nt=32][kt=4][lane]
#define W1C_N   (32 * 2 * 32)      // fp8 corr   [nt=32][ks=2][lane]
#define W2H_N   (16 * 16 * 32)     // bf16 main  [nt=16][ktg=16][lane]
#define W2C_N   (16 * 8 * 32)      // fp8 corr   [nt=16][kc=8][lane]

__device__ uint2 gW1H[W1H_N];
__device__ uint2 gW1c8H[W1C_N], gW1c8L[W1C_N];
__device__ uint2 gW2H[W2H_N];
__device__ uint2 gW2c8H[W2C_N], gW2c8L[W2C_N];
__device__ int g_idx_is_64;

// ---- smem byte offsets --------------------------------------------------
#define SMB_W1H    0
#define SMB_W1C8H  32768
#define SMB_W1C8L  49152
#define SMB_W2H    65536
#define SMB_W2C8H  131072
#define SMB_W2C8L  163840
#define SMB_B1     196608
#define SMB_B2     197632
#define SMEM_TOTAL 198144

// ---- helpers ------------------------------------------------------------
__device__ __forceinline__ uint32_t pkbf(float lo, float hi) {   // low half = lo
    uint32_t r;
    asm("cvt.rn.bf16x2.f32 %0, %1, %2;" : "=r"(r) : "f"(hi), "f"(lo));
    return r;
}
__device__ __forceinline__ float bflo(uint32_t p) { return __uint_as_float(p << 16); }
__device__ __forceinline__ float bfhi(uint32_t p) { return __uint_as_float(p & 0xffff0000u); }

// pack 4 floats -> 4 e4m3 bytes (byte0 = f0)
__device__ __forceinline__ uint32_t pk8x4(float f0, float f1, float f2, float f3) {
    uint32_t r;
    asm("{ .reg .b16 lo, hi;\n\t"
        "cvt.rn.satfinite.e4m3x2.f32 lo, %2, %1;\n\t"
        "cvt.rn.satfinite.e4m3x2.f32 hi, %4, %3;\n\t"
        "mov.b32 %0, {lo, hi}; }"
        : "=r"(r) : "f"(f0), "f"(f1), "f"(f2), "f"(f3));
    return r;
}

__device__ __forceinline__ void mma16816(float* c, const uint32_t* a, uint2 b) {
    asm volatile(
        "mma.sync.aligned.m16n8k16.row.col.f32.bf16.bf16.f32 "
        "{%0,%1,%2,%3}, {%4,%5,%6,%7}, {%8,%9}, {%0,%1,%2,%3};"
        : "+f"(c[0]), "+f"(c[1]), "+f"(c[2]), "+f"(c[3])
        : "r"(a[0]), "r"(a[1]), "r"(a[2]), "r"(a[3]), "r"(b.x), "r"(b.y));
}
__device__ __forceinline__ void mma_fp8(float* c, const uint32_t* a, uint2 b) {
    asm volatile(
        "mma.sync.aligned.m16n8k32.row.col.f32.e4m3.e4m3.f32 "
        "{%0,%1,%2,%3}, {%4,%5,%6,%7}, {%8,%9}, {%0,%1,%2,%3};"
        : "+f"(c[0]), "+f"(c[1]), "+f"(c[2]), "+f"(c[3])
        : "r"(a[0]), "r"(a[1]), "r"(a[2]), "r"(a[3]), "r"(b.x), "r"(b.y));
}
__device__ __forceinline__ void red_add2(float* p, float a, float b) {
    asm volatile("red.global.add.v2.f32 [%0], {%1, %2};"
                 :: "l"(p), "f"(a), "f"(b) : "memory");
}
__device__ __forceinline__ void prefetch_l2(const void* p) {
    asm volatile("prefetch.global.L2 [%0];" :: "l"(p));
}

// inverse of the GEMM2 correction K-permutation pi2:
// khat bits (a5..a0) -> col = a5*32 + a4*16 + a1*8 + a3*4 + a2*2 + a0
__device__ __forceinline__ int p2inv(int kk) {
    return ((kk >> 5) & 1) * 32 + ((kk >> 4) & 1) * 16 + ((kk >> 1) & 1) * 8 +
           ((kk >> 3) & 1) * 4 + ((kk >> 2) & 1) * 2 + (kk & 1);
}

// ---- prep: weights -> fragment-linear bf16 main + fp8 correction --------
__global__ void prep_weights(const float* __restrict__ W1,
                             const float* __restrict__ W2,
                             const int*   __restrict__ idx32) {
    // idx dtype probe (block 0, warp 0): odd words all zero <=> int64
    if (blockIdx.x == 0 && threadIdx.x < 32) {
        int ok = (idx32[2 * threadIdx.x + 1] == 0);
        unsigned m = __ballot_sync(0xffffffffu, ok);
        if (threadIdx.x == 0) g_idx_is_64 = (m == 0xffffffffu);
    }

    int t = blockIdx.x * blockDim.x + threadIdx.x;
    if (t < W1H_N) {
        // W1 bf16 main fragments
        int lane = t & 31, kt = (t >> 5) & 3, nt = t >> 7;
        int n = nt * 8 + (lane >> 2), k0 = kt * 16 + (lane & 3) * 2;
        gW1H[t] = make_uint2(
            pkbf(W1[k0 * HID_DIM + n],       W1[(k0 + 1) * HID_DIM + n]),
            pkbf(W1[(k0 + 8) * HID_DIM + n], W1[(k0 + 9) * HID_DIM + n]));
    } else if (t < W1H_N + W1C_N) {
        // W1 fp8 correction fragments (identity K layout)
        int u = t - W1H_N;
        int lane = u & 31, ks = (u >> 5) & 1, nt = u >> 6;
        int n = nt * 8 + (lane >> 2), k0 = 32 * ks + (lane & 3) * 4;
        float wh[8], wl[8];
        #pragma unroll
        for (int i = 0; i < 8; ++i) {
            int k = k0 + (i & 3) + (i >> 2) * 16;
            float w = W1[k * HID_DIM + n];
            uint32_t hb = pkbf(w, 0.f);
            wh[i] = w;
            wl[i] = (w - bflo(hb)) * 256.f;
        }
        gW1c8H[u] = make_uint2(pk8x4(wh[0], wh[1], wh[2], wh[3]),
                               pk8x4(wh[4], wh[5], wh[6], wh[7]));
        gW1c8L[u] = make_uint2(pk8x4(wl[0], wl[1], wl[2], wl[3]),
                               pk8x4(wl[4], wl[5], wl[6], wl[7]));
    } else if (t < W1H_N + W1C_N + W2H_N) {
        // W2 bf16 main fragments
        int u = t - W1H_N - W1C_N;
        int lane = u & 31, kt = (u >> 5) & 15, nt = u >> 9;
        int n = nt * 8 + (lane >> 2), k0 = kt * 16 + (lane & 3) * 2;
        gW2H[u] = make_uint2(
            pkbf(W2[k0 * OUT_DIM + n],       W2[(k0 + 1) * OUT_DIM + n]),
            pkbf(W2[(k0 + 8) * OUT_DIM + n], W2[(k0 + 9) * OUT_DIM + n]));
    } else if (t < W1H_N + W1C_N + W2H_N + W2C_N) {
        // W2 fp8 correction fragments, K permuted by pi2
        int u = t - W1H_N - W1C_N - W2H_N;
        int lane = u & 31, kc = (u >> 5) & 7, nt = u >> 8;
        int c = kc >> 1, ks = kc & 1;
        int n = nt * 8 + (lane >> 2), tig = lane & 3;
        float wh[8], wl[8];
        #pragma unroll
        for (int i = 0; i < 8; ++i) {
            int khat = 32 * ks + (i >> 2) * 16 + 4 * tig + (i & 3);
            int row = c * 64 + p2inv(khat);
            float w = W2[row * OUT_DIM + n];
            uint32_t hb = pkbf(w, 0.f);
            wh[i] = w;
            wl[i] = (w - bflo(hb)) * 256.f;
        }
        gW2c8H[u] = make_uint2(pk8x4(wh[0], wh[1], wh[2], wh[3]),
                               pk8x4(wh[4], wh[5], wh[6], wh[7]));
        gW2c8L[u] = make_uint2(pk8x4(wl[0], wl[1], wl[2], wl[3]),
                               pk8x4(wl[4], wl[5], wl[6], wl[7]));
    }
}

// ---- main persistent fused kernel ---------------------------------------
__global__ __launch_bounds__(NTH, 1)
void item_encoder_mma(const float* __restrict__ x,
                      const int*   __restrict__ idx32,
                      const float* __restrict__ b1,
                      const float* __restrict__ b2,
                      float* __restrict__ out,
                      int n_items, int n_tiles)
{
    extern __shared__ char smc[];
    const uint2* sW1H   = (const uint2*)(smc + SMB_W1H);
    const uint2* sW1c8H = (const uint2*)(smc + SMB_W1C8H);
    const uint2* sW1c8L = (const uint2*)(smc + SMB_W1C8L);
    const uint2* sW2H   = (const uint2*)(smc + SMB_W2H);
    const uint2* sW2c8H = (const uint2*)(smc + SMB_W2C8H);
    const uint2* sW2c8L = (const uint2*)(smc + SMB_W2C8L);
    float* b1s = (float*)(smc + SMB_B1);
    float* b2s = (float*)(smc + SMB_B2);

    const int tid = threadIdx.x;
    const int wid = tid >> 5, lane = tid & 31;
    const int gid = lane >> 2, tig = lane & 3;

    // ---- one-time prologue: stage weights + biases ----------------------
    {
        uint4* d = (uint4*)smc;
        const uint4* s;
        s = (const uint4*)gW1H;
        for (int i = tid; i < 2048; i += NTH) d[i] = s[i];
        s = (const uint4*)gW1c8H;
        for (int i = tid; i < 1024; i += NTH) d[2048 + i] = s[i];
        s = (const uint4*)gW1c8L;
        for (int i = tid; i < 1024; i += NTH) d[3072 + i] = s[i];
        s = (const uint4*)gW2H;
        for (int i = tid; i < 4096; i += NTH) d[4096 + i] = s[i];
        s = (const uint4*)gW2c8H;
        for (int i = tid; i < 2048; i += NTH) d[8192 + i] = s[i];
        s = (const uint4*)gW2c8L;
        for (int i = tid; i < 2048; i += NTH) d[10240 + i] = s[i];
        b1s[tid] = b1[tid];
        if (tid < TM) b2s[tid] = b2[tid];
    }
    __syncthreads();
    const int is64 = g_idx_is_64;
    const long long stride_items = (long long)gridDim.x * TM;

    // ---- persistent tile loop (no syncs inside) -------------------------
    for (int tile = blockIdx.x; tile < n_tiles; tile += gridDim.x) {
        const long long item0 = (long long)tile * TM;

        // L2 prefetch of next tile's x
        {
            long long pfi = item0 + stride_items + (tid >> 1);
            if (pfi < n_items)
                prefetch_l2((const char*)(x + pfi * IN_DIM) + (tid & 1) * 128);
        }

        const long long r0 = item0 + wid * 16 + gid;
        const long long r1 = r0 + 8;
        const bool v0ok = (r0 < n_items), v1ok = (r1 < n_items);

        // ---- x bf16 main A-fragments ------------------------------------
        uint32_t xh[4][4];
        {
            const float* p0 = x + r0 * IN_DIM + tig * 2;
            const float* p1 = x + r1 * IN_DIM + tig * 2;
            #pragma unroll
            for (int kt = 0; kt < 4; ++kt) {
                float2 f0 = make_float2(0.f, 0.f), f1 = f0, f2 = f0, f3 = f0;
                if (v0ok) { f0 = *(const float2*)(p0 + kt * 16);
                            f2 = *(const float2*)(p0 + kt * 16 + 8); }
                if (v1ok) { f1 = *(const float2*)(p1 + kt * 16);
                            f3 = *(const float2*)(p1 + kt * 16 + 8); }
                xh[kt][0] = pkbf(f0.x, f0.y);
                xh[kt][1] = pkbf(f1.x, f1.y);
                xh[kt][2] = pkbf(f2.x, f2.y);
                xh[kt][3] = pkbf(f3.x, f3.y);
            }
        }
        // ---- x fp8 correction A-fragments (k32 layout) -------------------
        uint32_t xf8h[2][4], xf8l[2][4];
        {
            #pragma unroll
            for (int ks = 0; ks < 2; ++ks) {
                #pragma unroll
                for (int rg = 0; rg < 4; ++rg) {       // a0..a3
                    long long rr = (rg & 1) ? r1 : r0;
                    bool ok = (rg & 1) ? v1ok : v0ok;
                    int kb = 32 * ks + ((rg >> 1) ? 16 : 0) + 4 * tig;
                    float4 f = make_float4(0.f, 0.f, 0.f, 0.f);
                    if (ok) f = *(const float4*)(x + rr * IN_DIM + kb);
                    xf8h[ks][rg] = pk8x4(f.x, f.y, f.z, f.w);
                    uint32_t h01 = pkbf(f.x, f.y), h23 = pkbf(f.z, f.w);
                    xf8l[ks][rg] = pk8x4((f.x - bflo(h01)) * 256.f,
                                         (f.y - bfhi(h01)) * 256.f,
                                         (f.z - bflo(h23)) * 256.f,
                                         (f.w - bfhi(h23)) * 256.f);
                }
            }
        }
        // bins
        int bin0 = -1, bin1 = -1;
        if (v0ok) bin0 = is64 ? (int)((const long long*)idx32)[r0] : idx32[r0];
        if (v1ok) bin1 = is64 ? (int)((const long long*)idx32)[r1] : idx32[r1];

        float o[16][4];
        #pragma unroll
        for (int nt = 0; nt < 16; ++nt)
            #pragma unroll
            for (int q = 0; q < 4; ++q) o[nt][q] = 0.f;

        // ---- 4 hidden chunks of 64 --------------------------------------
        #pragma unroll 1
        for (int c = 0; c < 4; ++c) {
            // GEMM1 main (bf16) into c1
            float c1[8][4];
            #pragma unroll
            for (int j = 0; j < 8; ++j) {
                #pragma unroll
                for (int q = 0; q < 4; ++q) c1[j][q] = 0.f;
                int fb = ((c * 8 + j) * 4) * 32 + lane;
                #pragma unroll
                for (int kt = 0; kt < 4; ++kt)
                    mma16816(c1[j], xh[kt], sW1H[fb + kt * 32]);
            }
            // GEMM1 corrections (fp8) + combine + bias + relu
            float v[8][4];
            #pragma unroll
            for (int j = 0; j < 8; ++j) {
                float cc[4] = {0.f, 0.f, 0.f, 0.f};
                int fb8 = ((c * 8 + j) * 2) * 32 + lane;
                #pragma unroll
                for (int ks = 0; ks < 2; ++ks) {
                    mma_fp8(cc, xf8h[ks], sW1c8L[fb8 + ks * 32]);
                    mma_fp8(cc, xf8l[ks], sW1c8H[fb8 + ks * 32]);
                }
                float2 bb = *(const float2*)&b1s[c * 64 + j * 8 + tig * 2];
                v[j][0] = fmaxf(fmaf(cc[0], INV256, c1[j][0]) + bb.x, 0.f);
                v[j][1] = fmaxf(fmaf(cc[1], INV256, c1[j][1]) + bb.y, 0.f);
                v[j][2] = fmaxf(fmaf(cc[2], INV256, c1[j][2]) + bb.x, 0.f);
                v[j][3] = fmaxf(fmaf(cc[3], INV256, c1[j][3]) + bb.y, 0.f);
            }

            // re-split: bf16 main A-frags + scaled residuals
            uint32_t ah[4][4];
            float r[8][4];
            #pragma unroll
            for (int j = 0; j < 8; ++j) {
                uint32_t p01 = pkbf(v[j][0], v[j][1]);
                uint32_t p23 = pkbf(v[j][2], v[j][3]);
                int kt = j >> 1, s = (j & 1) * 2;
                ah[kt][s] = p01; ah[kt][s + 1] = p23;
                r[j][0] = (v[j][0] - bflo(p01)) * 256.f;
                r[j][1] = (v[j][1] - bfhi(p01)) * 256.f;
                r[j][2] = (v[j][2] - bflo(p23)) * 256.f;
                r[j][3] = (v[j][3] - bfhi(p23)) * 256.f;
            }
            // fp8 A-frags in pi2 K-order (pure register packing, no shuffles)
            uint32_t ah8[2][4], al8[2][4];
            #pragma unroll
            for (int ks = 0; ks < 2; ++ks) {
                int j0 = 4 * ks;
                ah8[ks][0] = pk8x4(v[j0][0], v[j0][1], v[j0+1][0], v[j0+1][1]);
                ah8[ks][1] = pk8x4(v[j0][2], v[j0][3], v[j0+1][2], v[j0+1][3]);
                ah8[ks][2] = pk8x4(v[j0+2][0], v[j0+2][1], v[j0+3][0], v[j0+3][1]);
                ah8[ks][3] = pk8x4(v[j0+2][2], v[j0+2][3], v[j0+3][2], v[j0+3][3]);
                al8[ks][0] = pk8x4(r[j0][0], r[j0][1], r[j0+1][0], r[j0+1][1]);
                al8[ks][1] = pk8x4(r[j0][2], r[j0][3], r[j0+1][2], r[j0+1][3]);
                al8[ks][2] = pk8x4(r[j0+2][0], r[j0+2][1], r[j0+3][0], r[j0+3][1]);
                al8[ks][3] = pk8x4(r[j0+2][2], r[j0+2][3], r[j0+3][2], r[j0+3][3]);
            }

            // GEMM2: main (bf16) + corrections (fp8, folded per nt)
            #pragma unroll
            for (int nt = 0; nt < 16; ++nt) {
                int fb = (nt * 16 + c * 4) * 32 + lane;
                #pragma unroll
                for (int kt = 0; kt < 4; ++kt)
                    mma16816(o[nt], ah[kt], sW2H[fb + kt * 32]);
                float oc[4] = {0.f, 0.f, 0.f, 0.f};
                int fb8 = (nt * 8 + c * 2) * 32 + lane;
                #pragma unroll
                for (int ks = 0; ks < 2; ++ks) {
                    mma_fp8(oc, ah8[ks], sW2c8L[fb8 + ks * 32]);
                    mma_fp8(oc, al8[ks], sW2c8H[fb8 + ks * 32]);
                }
                #pragma unroll
                for (int q = 0; q < 4; ++q)
                    o[nt][q] = fmaf(oc[q], INV256, o[nt][q]);
            }
        }

        // ---- epilogue: +b2, scatter-add ---------------------------------
        #pragma unroll
        for (int nt = 0; nt < 16; ++nt) {
            int col = nt * 8 + tig * 2;
            float2 bb = *(const float2*)&b2s[col];
            if (bin0 >= 0)
                red_add2(out + (size_t)bin0 * OUT_DIM + col,
                         o[nt][0] + bb.x, o[nt][1] + bb.y);
            if (bin1 >= 0)
                red_add2(out + (size_t)bin1 * OUT_DIM + col,
                         o[nt][2] + bb.x, o[nt][3] + bb.y);
        }
    }
}

extern "C" void kernel_launch(void* const* d_in, const int* in_sizes, int n_in,
                              void* d_out, int out_size)
{
    const float* x     = (const float*)d_in[0];
    const int*   idx32 = (const int*)d_in[1];
    int wbase = 3;
    if (n_in >= 3 && in_sizes[2] == IN_DIM * HID_DIM) wbase = 2;
    const float* W1 = (const float*)d_in[wbase + 0];
    const float* b1 = (const float*)d_in[wbase + 1];
    const float* W2 = (const float*)d_in[wbase + 2];
    const float* b2 = (const float*)d_in[wbase + 3];
    float* out = (float*)d_out;

    const int n_items = in_sizes[0] / IN_DIM;
    const int n_tiles = (n_items + TM - 1) / TM;

    cudaFuncSetAttribute(item_encoder_mma,
                         cudaFuncAttributeMaxDynamicSharedMemorySize, SMEM_TOTAL);

    cudaMemsetAsync(d_out, 0, (size_t)out_size * sizeof(float), (cudaStream_t)0);

    const int prep_items = W1H_N + W1C_N + W2H_N + W2C_N;   // 18432
    prep_weights<<<(prep_items + NTH - 1) / NTH, NTH, 0, (cudaStream_t)0>>>(W1, W2, idx32);

    item_encoder_mma<<<NSM, NTH, SMEM_TOTAL, (cudaStream_t)0>>>(
        x, idx32, b1, b2, out, n_items, n_tiles);
}

// round 8
// speedup vs baseline: 1.0104x; 1.0104x over previous
#include <cuda_runtime.h>
#include <cstdint>

#define IN_DIM   64
#define HID_DIM  256
#define OUT_DIM  128
#define TM       128
#define NTH      256
#define NSM      148
#define INV256   0.00390625f

// fragment array sizes (uint2 elements)
#define W1_FRAGS (32 * 4 * 32)     // bf16 H+L  [nt=32][kt=4][lane]
#define W2H_N    (16 * 16 * 32)    // bf16 main [nt=16][ktg=16][lane]
#define W2C_N    (16 * 8 * 32)     // fp8 corr  [nt=16][kc=8][lane]

__device__ uint2 gW1H[W1_FRAGS], gW1L[W1_FRAGS];
__device__ uint2 gW2H[W2H_N];
__device__ uint2 gW2c8H[W2C_N], gW2c8L[W2C_N];
__device__ int g_idx_is_64;

// ---- smem byte offsets --------------------------------------------------
#define SMB_W1H    0
#define SMB_W1L    32768
#define SMB_W2H    65536
#define SMB_W2C8H  131072
#define SMB_W2C8L  163840
#define SMB_B1     196608
#define SMB_B2     197632
#define SMEM_TOTAL 198144

// ---- helpers ------------------------------------------------------------
__device__ __forceinline__ uint32_t pkbf(float lo, float hi) {   // low half = lo
    uint32_t r;
    asm("cvt.rn.bf16x2.f32 %0, %1, %2;" : "=r"(r) : "f"(hi), "f"(lo));
    return r;
}
__device__ __forceinline__ float bflo(uint32_t p) { return __uint_as_float(p << 16); }
__device__ __forceinline__ float bfhi(uint32_t p) { return __uint_as_float(p & 0xffff0000u); }

// pack 4 floats -> 4 e4m3 bytes (byte0 = f0)
__device__ __forceinline__ uint32_t pk8x4(float f0, float f1, float f2, float f3) {
    uint32_t r;
    asm("{ .reg .b16 lo, hi;\n\t"
        "cvt.rn.satfinite.e4m3x2.f32 lo, %2, %1;\n\t"
        "cvt.rn.satfinite.e4m3x2.f32 hi, %4, %3;\n\t"
        "mov.b32 %0, {lo, hi}; }"
        : "=r"(r) : "f"(f0), "f"(f1), "f"(f2), "f"(f3));
    return r;
}
// residuals vs packed bf16 pair, scaled x256
__device__ __forceinline__ float reslo(float v, uint32_t p) { return (v - bflo(p)) * 256.f; }
__device__ __forceinline__ float reshi(float v, uint32_t p) { return (v - bfhi(p)) * 256.f; }

__device__ __forceinline__ void mma16816(float* c, const uint32_t* a, uint2 b) {
    asm volatile(
        "mma.sync.aligned.m16n8k16.row.col.f32.bf16.bf16.f32 "
        "{%0,%1,%2,%3}, {%4,%5,%6,%7}, {%8,%9}, {%0,%1,%2,%3};"
        : "+f"(c[0]), "+f"(c[1]), "+f"(c[2]), "+f"(c[3])
        : "r"(a[0]), "r"(a[1]), "r"(a[2]), "r"(a[3]), "r"(b.x), "r"(b.y));
}
__device__ __forceinline__ void mma_fp8(float* c, const uint32_t* a, uint2 b) {
    asm volatile(
        "mma.sync.aligned.m16n8k32.row.col.f32.e4m3.e4m3.f32 "
        "{%0,%1,%2,%3}, {%4,%5,%6,%7}, {%8,%9}, {%0,%1,%2,%3};"
        : "+f"(c[0]), "+f"(c[1]), "+f"(c[2]), "+f"(c[3])
        : "r"(a[0]), "r"(a[1]), "r"(a[2]), "r"(a[3]), "r"(b.x), "r"(b.y));
}
__device__ __forceinline__ void red_add2(float* p, float a, float b) {
    asm volatile("red.global.add.v2.f32 [%0], {%1, %2};"
                 :: "l"(p), "f"(a), "f"(b) : "memory");
}
__device__ __forceinline__ void prefetch_l2(const void* p) {
    asm volatile("prefetch.global.L2 [%0];" :: "l"(p));
}
__device__ __forceinline__ void split_pair(float a, float b, uint32_t& h, uint32_t& l) {
    h = pkbf(a, b);
    l = pkbf(a - bflo(h), b - bfhi(h));
}

// inverse of the GEMM2 correction K-permutation pi2 (validated in R7):
// khat bits (a5..a0) -> col = a5*32 + a4*16 + a1*8 + a3*4 + a2*2 + a0
__device__ __forceinline__ int p2inv(int kk) {
    return ((kk >> 5) & 1) * 32 + ((kk >> 4) & 1) * 16 + ((kk >> 1) & 1) * 8 +
           ((kk >> 3) & 1) * 4 + ((kk >> 2) & 1) * 2 + (kk & 1);
}

// ---- prep: weights -> fragment-linear layouts ---------------------------
__global__ void prep_weights(const float* __restrict__ W1,
                             const float* __restrict__ W2,
                             const int*   __restrict__ idx32) {
    if (blockIdx.x == 0 && threadIdx.x < 32) {
        int ok = (idx32[2 * threadIdx.x + 1] == 0);
        unsigned m = __ballot_sync(0xffffffffu, ok);
        if (threadIdx.x == 0) g_idx_is_64 = (m == 0xffffffffu);
    }

    int t = blockIdx.x * blockDim.x + threadIdx.x;
    if (t < W1_FRAGS) {
        // W1 bf16 hi/lo fragments (3-term GEMM1)
        int lane = t & 31, kt = (t >> 5) & 3, nt = t >> 7;
        int n = nt * 8 + (lane >> 2), k0 = kt * 16 + (lane & 3) * 2;
        float w00 = W1[k0 * HID_DIM + n],       w01 = W1[(k0 + 1) * HID_DIM + n];
        float w10 = W1[(k0 + 8) * HID_DIM + n], w11 = W1[(k0 + 9) * HID_DIM + n];
        uint32_t h0, l0, h1, l1;
        split_pair(w00, w01, h0, l0);
        split_pair(w10, w11, h1, l1);
        gW1H[t] = make_uint2(h0, h1);
        gW1L[t] = make_uint2(l0, l1);
    } else if (t < W1_FRAGS + W2H_N) {
        // W2 bf16 main fragments
        int u = t - W1_FRAGS;
        int lane = u & 31, kt = (u >> 5) & 15, nt = u >> 9;
        int n = nt * 8 + (lane >> 2), k0 = kt * 16 + (lane & 3) * 2;
        gW2H[u] = make_uint2(
            pkbf(W2[k0 * OUT_DIM + n],       W2[(k0 + 1) * OUT_DIM + n]),
            pkbf(W2[(k0 + 8) * OUT_DIM + n], W2[(k0 + 9) * OUT_DIM + n]));
    } else if (t < W1_FRAGS + W2H_N + W2C_N) {
        // W2 fp8 correction fragments, K permuted by pi2
        int u = t - W1_FRAGS - W2H_N;
        int lane = u & 31, kc = (u >> 5) & 7, nt = u >> 8;
        int c = kc >> 1, ks = kc & 1;
        int n = nt * 8 + (lane >> 2), tig = lane & 3;
        float wh[8], wl[8];
        #pragma unroll
        for (int i = 0; i < 8; ++i) {
            int khat = 32 * ks + (i >> 2) * 16 + 4 * tig + (i & 3);
            int row = c * 64 + p2inv(khat);
            float w = W2[row * OUT_DIM + n];
            uint32_t hb = pkbf(w, 0.f);
            wh[i] = w;
            wl[i] = (w - bflo(hb)) * 256.f;
        }
        gW2c8H[u] = make_uint2(pk8x4(wh[0], wh[1], wh[2], wh[3]),
                               pk8x4(wh[4], wh[5], wh[6], wh[7]));
        gW2c8L[u] = make_uint2(pk8x4(wl[0], wl[1], wl[2], wl[3]),
                               pk8x4(wl[4], wl[5], wl[6], wl[7]));
    }
}

// ---- main persistent fused kernel ---------------------------------------
__global__ __launch_bounds__(NTH, 1)
void item_encoder_mma(const float* __restrict__ x,
                      const int*   __restrict__ idx32,
                      const float* __restrict__ b1,
                      const float* __restrict__ b2,
                      float* __restrict__ out,
                      int n_items, int n_tiles)
{
    extern __shared__ char smc[];
    const uint2* sW1H   = (const uint2*)(smc + SMB_W1H);
    const uint2* sW1L   = (const uint2*)(smc + SMB_W1L);
    const uint2* sW2H   = (const uint2*)(smc + SMB_W2H);
    const uint2* sW2c8H = (const uint2*)(smc + SMB_W2C8H);
    const uint2* sW2c8L = (const uint2*)(smc + SMB_W2C8L);
    float* b1s = (float*)(smc + SMB_B1);
    float* b2s = (float*)(smc + SMB_B2);

    const int tid = threadIdx.x;
    const int wid = tid >> 5, lane = tid & 31;
    const int gid = lane >> 2, tig = lane & 3;

    // ---- one-time prologue: stage weights + biases ----------------------
    {
        uint4* d = (uint4*)smc;
        const uint4* s;
        s = (const uint4*)gW1H;
        for (int i = tid; i < 2048; i += NTH) d[i] = s[i];
        s = (const uint4*)gW1L;
        for (int i = tid; i < 2048; i += NTH) d[2048 + i] = s[i];
        s = (const uint4*)gW2H;
        for (int i = tid; i < 4096; i += NTH) d[4096 + i] = s[i];
        s = (const uint4*)gW2c8H;
        for (int i = tid; i < 2048; i += NTH) d[8192 + i] = s[i];
        s = (const uint4*)gW2c8L;
        for (int i = tid; i < 2048; i += NTH) d[10240 + i] = s[i];
        b1s[tid] = b1[tid];
        if (tid < TM) b2s[tid] = b2[tid];
    }
    __syncthreads();
    const int is64 = g_idx_is_64;
    const long long stride_items = (long long)gridDim.x * TM;

    // ---- persistent tile loop (no syncs inside) -------------------------
    for (int tile = blockIdx.x; tile < n_tiles; tile += gridDim.x) {
        const long long item0 = (long long)tile * TM;

        // L2 prefetch of next tile's x
        {
            long long pfi = item0 + stride_items + (tid >> 1);
            if (pfi < n_items)
                prefetch_l2((const char*)(x + pfi * IN_DIM) + (tid & 1) * 128);
        }

        const long long r0 = item0 + wid * 16 + gid;
        const long long r1 = r0 + 8;
        const bool v0ok = (r0 < n_items), v1ok = (r1 < n_items);

        // ---- x bf16 hi/lo A-fragments -----------------------------------
        uint32_t xh[4][4], xl[4][4];
        {
            const float* p0 = x + r0 * IN_DIM + tig * 2;
            const float* p1 = x + r1 * IN_DIM + tig * 2;
            #pragma unroll
            for (int kt = 0; kt < 4; ++kt) {
                float2 f0 = make_float2(0.f, 0.f), f1 = f0, f2 = f0, f3 = f0;
                if (v0ok) { f0 = *(const float2*)(p0 + kt * 16);
                            f2 = *(const float2*)(p0 + kt * 16 + 8); }
                if (v1ok) { f1 = *(const float2*)(p1 + kt * 16);
                            f3 = *(const float2*)(p1 + kt * 16 + 8); }
                split_pair(f0.x, f0.y, xh[kt][0], xl[kt][0]);
                split_pair(f1.x, f1.y, xh[kt][1], xl[kt][1]);
                split_pair(f2.x, f2.y, xh[kt][2], xl[kt][2]);
                split_pair(f3.x, f3.y, xh[kt][3], xl[kt][3]);
            }
        }
        // bins
        int bin0 = -1, bin1 = -1;
        if (v0ok) bin0 = is64 ? (int)((const long long*)idx32)[r0] : idx32[r0];
        if (v1ok) bin1 = is64 ? (int)((const long long*)idx32)[r1] : idx32[r1];

        float o[16][4];
        #pragma unroll
        for (int nt = 0; nt < 16; ++nt)
            #pragma unroll
            for (int q = 0; q < 4; ++q) o[nt][q] = 0.f;

        // ---- 4 hidden chunks of 64 --------------------------------------
        #pragma unroll 1
        for (int c = 0; c < 4; ++c) {
            // GEMM1 (bf16, 3-term exact) into c1, then bias+relu in place
            float c1[8][4];
            #pragma unroll
            for (int j = 0; j < 8; ++j) {
                #pragma unroll
                for (int q = 0; q < 4; ++q) c1[j][q] = 0.f;
                int fb = ((c * 8 + j) * 4) * 32 + lane;
                #pragma unroll
                for (int kt = 0; kt < 4; ++kt) {
                    uint2 bh = sW1H[fb + kt * 32];
                    uint2 bl = sW1L[fb + kt * 32];
                    mma16816(c1[j], xh[kt], bh);
                    mma16816(c1[j], xh[kt], bl);
                    mma16816(c1[j], xl[kt], bh);
                }
                float2 bb = *(const float2*)&b1s[c * 64 + j * 8 + tig * 2];
                c1[j][0] = fmaxf(c1[j][0] + bb.x, 0.f);
                c1[j][1] = fmaxf(c1[j][1] + bb.y, 0.f);
                c1[j][2] = fmaxf(c1[j][2] + bb.x, 0.f);
                c1[j][3] = fmaxf(c1[j][3] + bb.y, 0.f);
            }

            // bf16 main A-frags for GEMM2
            uint32_t ah[4][4];
            #pragma unroll
            for (int j = 0; j < 8; ++j) {
                int kt = j >> 1, s = (j & 1) * 2;
                ah[kt][s]     = pkbf(c1[j][0], c1[j][1]);
                ah[kt][s + 1] = pkbf(c1[j][2], c1[j][3]);
            }
            // fp8 A-frags in pi2 K-order; residuals computed inline (no r[] array)
            uint32_t ah8[2][4], al8[2][4];
            #pragma unroll
            for (int ks = 0; ks < 2; ++ks) {
                int j0 = 4 * ks;
                #pragma unroll
                for (int g = 0; g < 2; ++g) {          // row-pair group {j0,j0+1} / {j0+2,j0+3}
                    int ja = j0 + 2 * g, jb = ja + 1;
                    uint32_t pa0 = ah[ja >> 1][(ja & 1) * 2];
                    uint32_t pa1 = ah[ja >> 1][(ja & 1) * 2 + 1];
                    uint32_t pb0 = ah[jb >> 1][(jb & 1) * 2];
                    uint32_t pb1 = ah[jb >> 1][(jb & 1) * 2 + 1];
                    ah8[ks][2 * g]     = pk8x4(c1[ja][0], c1[ja][1], c1[jb][0], c1[jb][1]);
                    ah8[ks][2 * g + 1] = pk8x4(c1[ja][2], c1[ja][3], c1[jb][2], c1[jb][3]);
                    al8[ks][2 * g]     = pk8x4(reslo(c1[ja][0], pa0), reshi(c1[ja][1], pa0),
                                               reslo(c1[jb][0], pb0), reshi(c1[jb][1], pb0));
                    al8[ks][2 * g + 1] = pk8x4(reslo(c1[ja][2], pa1), reshi(c1[ja][3], pa1),
                                               reslo(c1[jb][2], pb1), reshi(c1[jb][3], pb1));
                }
            }

            // GEMM2: main (bf16) + fp8 corrections, folded per nt
            #pragma unroll
            for (int nt = 0; nt < 16; ++nt) {
                int fb = (nt * 16 + c * 4) * 32 + lane;
                #pragma unroll
                for (int kt = 0; kt < 4; ++kt)
                    mma16816(o[nt], ah[kt], sW2H[fb + kt * 32]);
                float oc[4] = {0.f, 0.f, 0.f, 0.f};
                int fb8 = (nt * 8 + c * 2) * 32 + lane;
                #pragma unroll
                for (int ks = 0; ks < 2; ++ks) {
                    mma_fp8(oc, ah8[ks], sW2c8L[fb8 + ks * 32]);
                    mma_fp8(oc, al8[ks], sW2c8H[fb8 + ks * 32]);
                }
                #pragma unroll
                for (int q = 0; q < 4; ++q)
                    o[nt][q] = fmaf(oc[q], INV256, o[nt][q]);
            }
        }

        // ---- epilogue: +b2, scatter-add ---------------------------------
        #pragma unroll
        for (int nt = 0; nt < 16; ++nt) {
            int col = nt * 8 + tig * 2;
            float2 bb = *(const float2*)&b2s[col];
            if (bin0 >= 0)
                red_add2(out + (size_t)bin0 * OUT_DIM + col,
                         o[nt][0] + bb.x, o[nt][1] + bb.y);
            if (bin1 >= 0)
                red_add2(out + (size_t)bin1 * OUT_DIM + col,
                         o[nt][2] + bb.x, o[nt][3] + bb.y);
        }
    }
}

extern "C" void kernel_launch(void* const* d_in, const int* in_sizes, int n_in,
                              void* d_out, int out_size)
{
    const float* x     = (const float*)d_in[0];
    const int*   idx32 = (const int*)d_in[1];
    int wbase = 3;
    if (n_in >= 3 && in_sizes[2] == IN_DIM * HID_DIM) wbase = 2;
    const float* W1 = (const float*)d_in[wbase + 0];
    const float* b1 = (const float*)d_in[wbase + 1];
    const float* W2 = (const float*)d_in[wbase + 2];
    const float* b2 = (const float*)d_in[wbase + 3];
    float* out = (float*)d_out;

    const int n_items = in_sizes[0] / IN_DIM;
    const int n_tiles = (n_items + TM - 1) / TM;

    cudaFuncSetAttribute(item_encoder_mma,
                         cudaFuncAttributeMaxDynamicSharedMemorySize, SMEM_TOTAL);

    cudaMemsetAsync(d_out, 0, (size_t)out_size * sizeof(float), (cudaStream_t)0);

    const int prep_items = W1_FRAGS + W2H_N + W2C_N;   // 16384
    prep_weights<<<prep_items / NTH, NTH, 0, (cudaStream_t)0>>>(W1, W2, idx32);

    item_encoder_mma<<<NSM, NTH, SMEM_TOTAL, (cudaStream_t)0>>>(
        x, idx32, b1, b2, out, n_items, n_tiles);
}

// round 9
// speedup vs baseline: 2.9394x; 2.9090x over previous
#include <cuda_runtime.h>
#include <cstdint>

#define IN_DIM   64
#define HID_DIM  256
#define OUT_DIM  128
#define TM       128
#define NTH      256
#define NSM      148

// fragment array sizes (uint2 elements)
#define W1_FRAGS (32 * 4 * 32)     // fp16 [nt=32][kt=4][lane]
#define W2_FRAGS (16 * 16 * 32)    // fp16 [nt=16][ktg=16][lane]

__device__ uint2 gW1[W1_FRAGS];
__device__ uint2 gW2[W2_FRAGS];
__device__ int g_idx_is_64;

// ---- smem byte offsets --------------------------------------------------
#define SMB_W1     0               // 32 KB
#define SMB_W2     32768           // 64 KB
#define SMB_B1     98304           // 1 KB
#define SMB_B2     99328           // 512 B
#define SMEM_TOTAL 99840           // ~97.5 KB -> 2 CTAs/SM

// ---- helpers ------------------------------------------------------------
__device__ __forceinline__ uint32_t pkhf(float lo, float hi) {   // low half = lo
    uint32_t r;
    asm("cvt.rn.f16x2.f32 %0, %1, %2;" : "=r"(r) : "f"(hi), "f"(lo));
    return r;
}
__device__ __forceinline__ void mma_f16(float* c, const uint32_t* a, uint2 b) {
    asm volatile(
        "mma.sync.aligned.m16n8k16.row.col.f32.f16.f16.f32 "
        "{%0,%1,%2,%3}, {%4,%5,%6,%7}, {%8,%9}, {%0,%1,%2,%3};"
        : "+f"(c[0]), "+f"(c[1]), "+f"(c[2]), "+f"(c[3])
        : "r"(a[0]), "r"(a[1]), "r"(a[2]), "r"(a[3]), "r"(b.x), "r"(b.y));
}
__device__ __forceinline__ void red_add2(float* p, float a, float b) {
    asm volatile("red.global.add.v2.f32 [%0], {%1, %2};"
                 :: "l"(p), "f"(a), "f"(b) : "memory");
}
__device__ __forceinline__ void prefetch_l2(const void* p) {
    asm volatile("prefetch.global.L2 [%0];" :: "l"(p));
}

// ---- prep: weights -> fp16 fragment-linear layout (+ idx dtype probe) ---
__global__ void prep_weights(const float* __restrict__ W1,
                             const float* __restrict__ W2,
                             const int*   __restrict__ idx32) {
    if (blockIdx.x == 0 && threadIdx.x < 32) {
        int ok = (idx32[2 * threadIdx.x + 1] == 0);
        unsigned m = __ballot_sync(0xffffffffu, ok);
        if (threadIdx.x == 0) g_idx_is_64 = (m == 0xffffffffu);
    }

    int t = blockIdx.x * blockDim.x + threadIdx.x;
    if (t < W1_FRAGS) {
        int lane = t & 31, kt = (t >> 5) & 3, nt = t >> 7;
        int n = nt * 8 + (lane >> 2), k0 = kt * 16 + (lane & 3) * 2;
        gW1[t] = make_uint2(
            pkhf(W1[k0 * HID_DIM + n],       W1[(k0 + 1) * HID_DIM + n]),
            pkhf(W1[(k0 + 8) * HID_DIM + n], W1[(k0 + 9) * HID_DIM + n]));
    } else if (t < W1_FRAGS + W2_FRAGS) {
        int u = t - W1_FRAGS;
        int lane = u & 31, kt = (u >> 5) & 15, nt = u >> 9;
        int n = nt * 8 + (lane >> 2), k0 = kt * 16 + (lane & 3) * 2;
        gW2[u] = make_uint2(
            pkhf(W2[k0 * OUT_DIM + n],       W2[(k0 + 1) * OUT_DIM + n]),
            pkhf(W2[(k0 + 8) * OUT_DIM + n], W2[(k0 + 9) * OUT_DIM + n]));
    }
}

// ---- main persistent fused kernel ---------------------------------------
__global__ __launch_bounds__(NTH, 2)
void item_encoder_mma(const float* __restrict__ x,
                      const int*   __restrict__ idx32,
                      const float* __restrict__ b1,
                      const float* __restrict__ b2,
                      float* __restrict__ out,
                      int n_items, int n_tiles)
{
    extern __shared__ char smc[];
    const uint2* sW1 = (const uint2*)(smc + SMB_W1);
    const uint2* sW2 = (const uint2*)(smc + SMB_W2);
    float* b1s = (float*)(smc + SMB_B1);
    float* b2s = (float*)(smc + SMB_B2);

    const int tid = threadIdx.x;
    const int wid = tid >> 5, lane = tid & 31;
    const int gid = lane >> 2, tig = lane & 3;

    // ---- one-time prologue: stage weights + biases ----------------------
    {
        uint4* d = (uint4*)smc;
        const uint4* s1 = (const uint4*)gW1;
        const uint4* s2 = (const uint4*)gW2;
        #pragma unroll 4
        for (int i = tid; i < 2048; i += NTH) d[i] = s1[i];
        #pragma unroll 4
        for (int i = tid; i < 4096; i += NTH) d[2048 + i] = s2[i];
        b1s[tid] = b1[tid];
        if (tid < TM) b2s[tid] = b2[tid];
    }
    __syncthreads();
    const int is64 = g_idx_is_64;
    const long long stride_items = (long long)gridDim.x * TM;

    // ---- persistent tile loop (no syncs inside) -------------------------
    for (int tile = blockIdx.x; tile < n_tiles; tile += gridDim.x) {
        const long long item0 = (long long)tile * TM;

        // L2 prefetch of next tile's x
        {
            long long pfi = item0 + stride_items + (tid >> 1);
            if (pfi < n_items)
                prefetch_l2((const char*)(x + pfi * IN_DIM) + (tid & 1) * 128);
        }

        const long long r0 = item0 + wid * 16 + gid;
        const long long r1 = r0 + 8;
        const bool v0ok = (r0 < n_items), v1ok = (r1 < n_items);

        // ---- x fp16 A-fragments -----------------------------------------
        uint32_t xh[4][4];
        {
            const float* p0 = x + r0 * IN_DIM + tig * 2;
            const float* p1 = x + r1 * IN_DIM + tig * 2;
            #pragma unroll
            for (int kt = 0; kt < 4; ++kt) {
                float2 f0 = make_float2(0.f, 0.f), f1 = f0, f2 = f0, f3 = f0;
                if (v0ok) { f0 = *(const float2*)(p0 + kt * 16);
                            f2 = *(const float2*)(p0 + kt * 16 + 8); }
                if (v1ok) { f1 = *(const float2*)(p1 + kt * 16);
                            f3 = *(const float2*)(p1 + kt * 16 + 8); }
                xh[kt][0] = pkhf(f0.x, f0.y);
                xh[kt][1] = pkhf(f1.x, f1.y);
                xh[kt][2] = pkhf(f2.x, f2.y);
                xh[kt][3] = pkhf(f3.x, f3.y);
            }
        }
        // bins (direct gmem loads)
        int bin0 = -1, bin1 = -1;
        if (v0ok) bin0 = is64 ? (int)((const long long*)idx32)[r0] : idx32[r0];
        if (v1ok) bin1 = is64 ? (int)((const long long*)idx32)[r1] : idx32[r1];

        float o[16][4];
        #pragma unroll
        for (int nt = 0; nt < 16; ++nt)
            #pragma unroll
            for (int q = 0; q < 4; ++q) o[nt][q] = 0.f;

        // ---- 4 hidden chunks of 64 --------------------------------------
        #pragma unroll 1
        for (int c = 0; c < 4; ++c) {
            // GEMM1: c1 = x @ W1[:, chunk]   (fp16 x fp16 -> fp32)
            float c1[8][4];
            #pragma unroll
            for (int j = 0; j < 8; ++j) {
                #pragma unroll
                for (int q = 0; q < 4; ++q) c1[j][q] = 0.f;
                int fb = ((c * 8 + j) * 4) * 32 + lane;
                #pragma unroll
                for (int kt = 0; kt < 4; ++kt)
                    mma_f16(c1[j], xh[kt], sW1[fb + kt * 32]);
                float2 bb = *(const float2*)&b1s[c * 64 + j * 8 + tig * 2];
                c1[j][0] = fmaxf(c1[j][0] + bb.x, 0.f);
                c1[j][1] = fmaxf(c1[j][1] + bb.y, 0.f);
                c1[j][2] = fmaxf(c1[j][2] + bb.x, 0.f);
                c1[j][3] = fmaxf(c1[j][3] + bb.y, 0.f);
            }

            // C-fragments -> fp16 A-fragments (in registers; c1 dies here)
            uint32_t ah[4][4];
            #pragma unroll
            for (int j = 0; j < 8; ++j) {
                int kt = j >> 1, s = (j & 1) * 2;
                ah[kt][s]     = pkhf(c1[j][0], c1[j][1]);
                ah[kt][s + 1] = pkhf(c1[j][2], c1[j][3]);
            }

            // GEMM2: O += H[:, chunk] @ W2[chunk, :]
            #pragma unroll
            for (int nt = 0; nt < 16; ++nt) {
                int fb = (nt * 16 + c * 4) * 32 + lane;
                #pragma unroll
                for (int kt = 0; kt < 4; ++kt)
                    mma_f16(o[nt], ah[kt], sW2[fb + kt * 32]);
            }
        }

        // ---- epilogue: +b2, scatter-add ---------------------------------
        #pragma unroll
        for (int nt = 0; nt < 16; ++nt) {
            int col = nt * 8 + tig * 2;
            float2 bb = *(const float2*)&b2s[col];
            if (bin0 >= 0)
                red_add2(out + (size_t)bin0 * OUT_DIM + col,
                         o[nt][0] + bb.x, o[nt][1] + bb.y);
            if (bin1 >= 0)
                red_add2(out + (size_t)bin1 * OUT_DIM + col,
                         o[nt][2] + bb.x, o[nt][3] + bb.y);
        }
    }
}

extern "C" void kernel_launch(void* const* d_in, const int* in_sizes, int n_in,
                              void* d_out, int out_size)
{
    const float* x     = (const float*)d_in[0];
    const int*   idx32 = (const int*)d_in[1];
    int wbase = 3;
    if (n_in >= 3 && in_sizes[2] == IN_DIM * HID_DIM) wbase = 2;
    const float* W1 = (const float*)d_in[wbase + 0];
    const float* b1 = (const float*)d_in[wbase + 1];
    const float* W2 = (const float*)d_in[wbase + 2];
    const float* b2 = (const float*)d_in[wbase + 3];
    float* out = (float*)d_out;

    const int n_items = in_sizes[0] / IN_DIM;
    const int n_tiles = (n_items + TM - 1) / TM;

    cudaFuncSetAttribute(item_encoder_mma,
                         cudaFuncAttributeMaxDynamicSharedMemorySize, SMEM_TOTAL);

    cudaMemsetAsync(d_out, 0, (size_t)out_size * sizeof(float), (cudaStream_t)0);

    const int prep_items = W1_FRAGS + W2_FRAGS;   // 12288
    prep_weights<<<prep_items / NTH, NTH, 0, (cudaStream_t)0>>>(W1, W2, idx32);

    item_encoder_mma<<<NSM, NTH, SMEM_TOTAL, (cudaStream_t)0>>>(
        x, idx32, b1, b2, out, n_items, n_tiles);
}

// round 10
// speedup vs baseline: 3.3337x; 1.1341x over previous
#include <cuda_runtime.h>
#include <cstdint>

#define IN_DIM   64
#define HID_DIM  256
#define OUT_DIM  128
#define TM       256          // items per CTA (32 rows per warp)
#define NTH      256
#define NSM      148

// fragment array sizes (uint2 elements)
#define W1_FRAGS (32 * 4 * 32)     // fp16 [nt=32][kt=4][lane]
#define W2_FRAGS (16 * 16 * 32)    // fp16 [nt=16][ktg=16][lane]

__device__ uint2 gW1[W1_FRAGS];
__device__ uint2 gW2[W2_FRAGS];
__device__ int g_idx_is_64;

// ---- smem byte offsets --------------------------------------------------
#define SMB_W1     0               // 32 KB
#define SMB_W2     32768           // 64 KB
#define SMB_B1     98304           // 1 KB
#define SMB_B2     99328           // 512 B
#define SMEM_TOTAL 99840

// ---- helpers ------------------------------------------------------------
__device__ __forceinline__ uint32_t pkhf(float lo, float hi) {   // low half = lo
    uint32_t r;
    asm("cvt.rn.f16x2.f32 %0, %1, %2;" : "=r"(r) : "f"(hi), "f"(lo));
    return r;
}
__device__ __forceinline__ void mma_f16(float* c, const uint32_t* a, uint2 b) {
    asm volatile(
        "mma.sync.aligned.m16n8k16.row.col.f32.f16.f16.f32 "
        "{%0,%1,%2,%3}, {%4,%5,%6,%7}, {%8,%9}, {%0,%1,%2,%3};"
        : "+f"(c[0]), "+f"(c[1]), "+f"(c[2]), "+f"(c[3])
        : "r"(a[0]), "r"(a[1]), "r"(a[2]), "r"(a[3]), "r"(b.x), "r"(b.y));
}
__device__ __forceinline__ void red_add2(float* p, float a, float b) {
    asm volatile("red.global.add.v2.f32 [%0], {%1, %2};"
                 :: "l"(p), "f"(a), "f"(b) : "memory");
}
__device__ __forceinline__ void prefetch_l2(const void* p) {
    asm volatile("prefetch.global.L2 [%0];" :: "l"(p));
}

// ---- prep: weights -> fp16 fragment-linear layout (+ idx dtype probe) ---
__global__ void prep_weights(const float* __restrict__ W1,
                             const float* __restrict__ W2,
                             const int*   __restrict__ idx32) {
    if (blockIdx.x == 0 && threadIdx.x < 32) {
        int ok = (idx32[2 * threadIdx.x + 1] == 0);
        unsigned m = __ballot_sync(0xffffffffu, ok);
        if (threadIdx.x == 0) g_idx_is_64 = (m == 0xffffffffu);
    }

    int t = blockIdx.x * blockDim.x + threadIdx.x;
    if (t < W1_FRAGS) {
        int lane = t & 31, kt = (t >> 5) & 3, nt = t >> 7;
        int n = nt * 8 + (lane >> 2), k0 = kt * 16 + (lane & 3) * 2;
        gW1[t] = make_uint2(
            pkhf(W1[k0 * HID_DIM + n],       W1[(k0 + 1) * HID_DIM + n]),
            pkhf(W1[(k0 + 8) * HID_DIM + n], W1[(k0 + 9) * HID_DIM + n]));
    } else if (t < W1_FRAGS + W2_FRAGS) {
        int u = t - W1_FRAGS;
        int lane = u & 31, kt = (u >> 5) & 15, nt = u >> 9;
        int n = nt * 8 + (lane >> 2), k0 = kt * 16 + (lane & 3) * 2;
        gW2[u] = make_uint2(
            pkhf(W2[k0 * OUT_DIM + n],       W2[(k0 + 1) * OUT_DIM + n]),
            pkhf(W2[(k0 + 8) * OUT_DIM + n], W2[(k0 + 9) * OUT_DIM + n]));
    }
}

// ---- main persistent fused kernel ---------------------------------------
__global__ __launch_bounds__(NTH, 1)
void item_encoder_mma(const float* __restrict__ x,
                      const int*   __restrict__ idx32,
                      const float* __restrict__ b1,
                      const float* __restrict__ b2,
                      float* __restrict__ out,
                      int n_items, int n_tiles)
{
    extern __shared__ char smc[];
    const uint2* sW1 = (const uint2*)(smc + SMB_W1);
    const uint2* sW2 = (const uint2*)(smc + SMB_W2);
    float* b1s = (float*)(smc + SMB_B1);
    float* b2s = (float*)(smc + SMB_B2);

    const int tid = threadIdx.x;
    const int wid = tid >> 5, lane = tid & 31;
    const int gid = lane >> 2, tig = lane & 3;

    // ---- one-time prologue: stage weights + biases ----------------------
    {
        uint4* d = (uint4*)smc;
        const uint4* s1 = (const uint4*)gW1;
        const uint4* s2 = (const uint4*)gW2;
        #pragma unroll 4
        for (int i = tid; i < 2048; i += NTH) d[i] = s1[i];
        #pragma unroll 4
        for (int i = tid; i < 4096; i += NTH) d[2048 + i] = s2[i];
        b1s[tid] = b1[tid];
        if (tid < TM / 2) b2s[tid] = b2[tid];
    }
    __syncthreads();
    const int is64 = g_idx_is_64;
    const long long stride_items = (long long)gridDim.x * TM;

    // ---- persistent tile loop (no syncs inside) -------------------------
    for (int tile = blockIdx.x; tile < n_tiles; tile += gridDim.x) {
        const long long item0 = (long long)tile * TM;

        // L2 prefetch of next tile's x (two 128B lines per thread)
        {
            long long pfi = item0 + stride_items + (tid >> 1);
            if (pfi < n_items)
                prefetch_l2((const char*)(x + pfi * IN_DIM) + (tid & 1) * 128);
            pfi += 128;
            if (pfi < n_items)
                prefetch_l2((const char*)(x + pfi * IN_DIM) + (tid & 1) * 128);
        }

        // this warp's 4 rows: base + {0, 8, 16, 24}; groups g0={+0,+8}, g1={+16,+24}
        const long long rb = item0 + wid * 32 + gid;
        bool vok[4];
        #pragma unroll
        for (int g = 0; g < 4; ++g) vok[g] = (rb + 8 * g) < n_items;

        // ---- x fp16 A-fragments for both groups -------------------------
        uint32_t xh[2][4][4];
        #pragma unroll
        for (int g2 = 0; g2 < 2; ++g2) {
            const float* p0 = x + (rb + 16 * g2) * IN_DIM + tig * 2;
            const float* p1 = p0 + 8 * IN_DIM;
            #pragma unroll
            for (int kt = 0; kt < 4; ++kt) {
                float2 f0 = make_float2(0.f, 0.f), f1 = f0, f2 = f0, f3 = f0;
                if (vok[2 * g2])     { f0 = *(const float2*)(p0 + kt * 16);
                                       f2 = *(const float2*)(p0 + kt * 16 + 8); }
                if (vok[2 * g2 + 1]) { f1 = *(const float2*)(p1 + kt * 16);
                                       f3 = *(const float2*)(p1 + kt * 16 + 8); }
                xh[g2][kt][0] = pkhf(f0.x, f0.y);
                xh[g2][kt][1] = pkhf(f1.x, f1.y);
                xh[g2][kt][2] = pkhf(f2.x, f2.y);
                xh[g2][kt][3] = pkhf(f3.x, f3.y);
            }
        }
        // bins (direct gmem loads)
        int bins[4];
        #pragma unroll
        for (int g = 0; g < 4; ++g) {
            long long rr = rb + 8 * g;
            bins[g] = vok[g] ? (is64 ? (int)((const long long*)idx32)[rr]
                                     : idx32[rr])
                             : -1;
        }

        float o[2][16][4];
        #pragma unroll
        for (int g2 = 0; g2 < 2; ++g2)
            #pragma unroll
            for (int nt = 0; nt < 16; ++nt)
                #pragma unroll
                for (int q = 0; q < 4; ++q) o[g2][nt][q] = 0.f;

        // ---- 4 hidden chunks of 64 --------------------------------------
        #pragma unroll 1
        for (int c = 0; c < 4; ++c) {
            // GEMM1: both groups share each W1 B-fragment load; c-frags are
            // consumed immediately (bias+relu+pack) so no c1 array stays live.
            uint32_t ah[2][4][4];
            #pragma unroll
            for (int j = 0; j < 8; ++j) {
                int fb = ((c * 8 + j) * 4) * 32 + lane;
                uint2 b0 = sW1[fb], b1f = sW1[fb + 32],
                      b2f = sW1[fb + 64], b3f = sW1[fb + 96];
                float2 bb = *(const float2*)&b1s[c * 64 + j * 8 + tig * 2];
                int kt = j >> 1, s = (j & 1) * 2;
                #pragma unroll
                for (int g2 = 0; g2 < 2; ++g2) {
                    float cc[4] = {0.f, 0.f, 0.f, 0.f};
                    mma_f16(cc, xh[g2][0], b0);
                    mma_f16(cc, xh[g2][1], b1f);
                    mma_f16(cc, xh[g2][2], b2f);
                    mma_f16(cc, xh[g2][3], b3f);
                    ah[g2][kt][s]     = pkhf(fmaxf(cc[0] + bb.x, 0.f),
                                             fmaxf(cc[1] + bb.y, 0.f));
                    ah[g2][kt][s + 1] = pkhf(fmaxf(cc[2] + bb.x, 0.f),
                                             fmaxf(cc[3] + bb.y, 0.f));
                }
            }

            // GEMM2: each W2 B-fragment load feeds both groups
            #pragma unroll
            for (int nt = 0; nt < 16; ++nt) {
                int fb = (nt * 16 + c * 4) * 32 + lane;
                uint2 b0 = sW2[fb], b1f = sW2[fb + 32],
                      b2f = sW2[fb + 64], b3f = sW2[fb + 96];
                mma_f16(o[0][nt], ah[0][0], b0);
                mma_f16(o[1][nt], ah[1][0], b0);
                mma_f16(o[0][nt], ah[0][1], b1f);
                mma_f16(o[1][nt], ah[1][1], b1f);
                mma_f16(o[0][nt], ah[0][2], b2f);
                mma_f16(o[1][nt], ah[1][2], b2f);
                mma_f16(o[0][nt], ah[0][3], b3f);
                mma_f16(o[1][nt], ah[1][3], b3f);
            }
        }

        // ---- epilogue: +b2, scatter-add (4 rows) ------------------------
        #pragma unroll
        for (int nt = 0; nt < 16; ++nt) {
            int col = nt * 8 + tig * 2;
            float2 bb = *(const float2*)&b2s[col];
            #pragma unroll
            for (int g2 = 0; g2 < 2; ++g2) {
                if (bins[2 * g2] >= 0)
                    red_add2(out + (size_t)bins[2 * g2] * OUT_DIM + col,
                             o[g2][nt][0] + bb.x, o[g2][nt][1] + bb.y);
                if (bins[2 * g2 + 1] >= 0)
                    red_add2(out + (size_t)bins[2 * g2 + 1] * OUT_DIM + col,
                             o[g2][nt][2] + bb.x, o[g2][nt][3] + bb.y);
            }
        }
    }
}

extern "C" void kernel_launch(void* const* d_in, const int* in_sizes, int n_in,
                              void* d_out, int out_size)
{
    const float* x     = (const float*)d_in[0];
    const int*   idx32 = (const int*)d_in[1];
    int wbase = 3;
    if (n_in >= 3 && in_sizes[2] == IN_DIM * HID_DIM) wbase = 2;
    const float* W1 = (const float*)d_in[wbase + 0];
    const float* b1 = (const float*)d_in[wbase + 1];
    const float* W2 = (const float*)d_in[wbase + 2];
    const float* b2 = (const float*)d_in[wbase + 3];
    float* out = (float*)d_out;

    const int n_items = in_sizes[0] / IN_DIM;
    const int n_tiles = (n_items + TM - 1) / TM;

    cudaFuncSetAttribute(item_encoder_mma,
                         cudaFuncAttributeMaxDynamicSharedMemorySize, SMEM_TOTAL);

    cudaMemsetAsync(d_out, 0, (size_t)out_size * sizeof(float), (cudaStream_t)0);

    const int prep_items = W1_FRAGS + W2_FRAGS;   // 12288
    prep_weights<<<prep_items / NTH, NTH, 0, (cudaStream_t)0>>>(W1, W2, idx32);

    item_encoder_mma<<<NSM, NTH, SMEM_TOTAL, (cudaStream_t)0>>>(
        x, idx32, b1, b2, out, n_items, n_tiles);
}